// round 8
// baseline (speedup 1.0000x reference)
#include <cuda_runtime.h>
#include <cuda_bf16.h>
#include <cstdint>

#define N_NODES 50000
#define N_EDGES 600000
#define HID     128
#define N_GRAPHS 32
#define D_OUT   3
#define SCAN_BLOCKS ((N_NODES + 255) / 256)   // 196

typedef unsigned long long u64;

// ---------------- scratch (device globals; no allocs) ----------------
__device__ int   g_cnt[N_NODES];
__device__ int   g_rowptr[N_NODES + 1];
__device__ int   g_cursor[N_NODES];
__device__ int   g_col[N_EDGES];
__device__ int   g_bsum[SCAN_BLOCKS];
__device__ __nv_bfloat16 g_P[(size_t)N_NODES * HID];   // messages, bf16
__device__ float g_bufA[(size_t)N_NODES * HID];
__device__ float g_bufB[(size_t)N_NODES * HID];
__device__ float g_gsum[N_GRAPHS * HID];
__device__ float g_gcnt[N_GRAPHS];

// ---------------- f32x2 helpers ----------------
__device__ __forceinline__ u64 pack_dup(float a) {
    u64 r;
    asm("mov.b64 %0, {%1,%1};" : "=l"(r) : "f"(a));
    return r;
}
__device__ __forceinline__ float2 unpack2(u64 v) {
    float2 r;
    asm("mov.b64 {%0,%1}, %2;" : "=f"(r.x), "=f"(r.y) : "l"(v));
    return r;
}
__device__ __forceinline__ void ffma2(u64& acc, u64 a, u64 b) {
    asm("fma.rn.f32x2 %0, %1, %2, %0;" : "+l"(acc) : "l"(a), "l"(b));
}

// =================================================================
// Dual-weight GEMM: out1 = A@W1^T + bias (relu opt) [fp32]
//                   out2 = A@W2^T                   [bf16]
// 128x128 block tile, 512 threads (16 warps), 8x4 microtile.
// lane (tid&31) = col-group of 4 cols; warp (tid>>5) = row-group of 8.
// A reads are warp-uniform broadcasts; W reads are one LDS.128/lane.
// =================================================================
template<int DUAL>
__global__ void __launch_bounds__(512, 1)
gemm_dw(const float* __restrict__ A,
        const float* __restrict__ W1, const float* __restrict__ W2,
        const float* __restrict__ bias,
        float* __restrict__ out1, __nv_bfloat16* __restrict__ out2,
        int M, int relu1) {
    extern __shared__ float smem[];
    float* sIn = smem;            // [row*128 + k], row-major
    float* sW1 = smem + 16384;    // k-major, float4 XOR-swizzled along cols
    float* sW2 = smem + 32768;

    int tid = threadIdx.x;
    int tx  = tid & 31;       // col group (4 cols: tx*4 .. +3)
    int wrp = tid >> 5;       // row group (8 rows: wrp*8 .. +7)
    int m0 = blockIdx.x * 128;

    // load input tile [128 rows x 128 k]
    #pragma unroll
    for (int it = 0; it < 8; it++) {
        int row = it * 16 + wrp;
        int grow = m0 + row;
        float4 v = make_float4(0.f, 0.f, 0.f, 0.f);
        if (grow < M) v = *(const float4*)(A + (size_t)grow * 128 + tx * 4);
        *(float4*)(sIn + row * 128 + tx * 4) = v;
    }
    // load W transposed into k-major with float4 XOR swizzle:
    // logical (k, c4) lives at sW[k*128 + ((c4 ^ ((k>>2)&31))<<2)]
    #pragma unroll
    for (int it = 0; it < 8; it++) {
        int col = it * 16 + wrp;
        float4 v1 = *(const float4*)(W1 + col * 128 + (tx << 2));
        int c4 = col >> 2;
        int cl = col & 3;
        float vv1[4] = {v1.x, v1.y, v1.z, v1.w};
        #pragma unroll
        for (int i = 0; i < 4; i++) {
            int k = (tx << 2) + i;       // (k>>2)&31 == tx
            sW1[k * 128 + ((c4 ^ tx) << 2) + cl] = vv1[i];
        }
        if (DUAL) {
            float4 v2 = *(const float4*)(W2 + col * 128 + (tx << 2));
            float vv2[4] = {v2.x, v2.y, v2.z, v2.w};
            #pragma unroll
            for (int i = 0; i < 4; i++) {
                int k = (tx << 2) + i;
                sW2[k * 128 + ((c4 ^ tx) << 2) + cl] = vv2[i];
            }
        }
    }
    __syncthreads();

    u64 acc1[8][2];
    u64 acc2[DUAL ? 8 : 1][2];
    #pragma unroll
    for (int r = 0; r < 8; r++) { acc1[r][0] = 0ull; acc1[r][1] = 0ull; }
    #pragma unroll
    for (int r = 0; r < (DUAL ? 8 : 1); r++) { acc2[r][0] = 0ull; acc2[r][1] = 0ull; }

    const float* aRow = sIn + wrp * 8 * 128;

    #pragma unroll 2
    for (int k2 = 0; k2 < 64; k2++) {
        int k = k2 * 2;
        // A pair-loads: warp-uniform LDS.64 broadcasts (k, k+1) per row
        float2 ap[8];
        #pragma unroll
        for (int r = 0; r < 8; r++)
            ap[r] = *(const float2*)(aRow + r * 128 + k);

        #pragma unroll
        for (int sub = 0; sub < 2; sub++) {
            int kk = k + sub;
            int swz = (kk >> 2) & 31;
            const float* w1r = sW1 + kk * 128;
            ulonglong2 b1 = *(const ulonglong2*)(w1r + ((tx ^ swz) << 2));
            u64 a2[8];
            #pragma unroll
            for (int r = 0; r < 8; r++)
                a2[r] = pack_dup(sub ? ap[r].y : ap[r].x);
            #pragma unroll
            for (int r = 0; r < 8; r++) {
                ffma2(acc1[r][0], a2[r], b1.x);
                ffma2(acc1[r][1], a2[r], b1.y);
            }
            if (DUAL) {
                const float* w2r = sW2 + kk * 128;
                ulonglong2 b2 = *(const ulonglong2*)(w2r + ((tx ^ swz) << 2));
                #pragma unroll
                for (int r = 0; r < 8; r++) {
                    ffma2(acc2[r][0], a2[r], b2.x);
                    ffma2(acc2[r][1], a2[r], b2.y);
                }
            }
        }
    }

    // epilogue: thread owns rows wrp*8..+7, cols tx*4..+3
    float bv[4];
    #pragma unroll
    for (int j = 0; j < 4; j++) bv[j] = bias[tx * 4 + j];

    #pragma unroll
    for (int r = 0; r < 8; r++) {
        int grow = m0 + wrp * 8 + r;
        if (grow < M) {
            float2 v0 = unpack2(acc1[r][0]);
            float2 v1 = unpack2(acc1[r][1]);
            float o[4] = {v0.x + bv[0], v0.y + bv[1], v1.x + bv[2], v1.y + bv[3]};
            if (relu1) {
                #pragma unroll
                for (int j = 0; j < 4; j++) o[j] = fmaxf(o[j], 0.0f);
            }
            *(float4*)(out1 + (size_t)grow * 128 + tx * 4) =
                make_float4(o[0], o[1], o[2], o[3]);
            if (DUAL) {
                float2 p0 = unpack2(acc2[r][0]);
                float2 p1 = unpack2(acc2[r][1]);
                __nv_bfloat162 h0 = __float22bfloat162_rn(p0);
                __nv_bfloat162 h1 = __float22bfloat162_rn(p1);
                uint2 pk;
                pk.x = *(uint32_t*)&h0;
                pk.y = *(uint32_t*)&h1;
                *(uint2*)(out2 + (size_t)grow * 128 + tx * 4) = pk;
            }
        }
    }
}

// ---------------- CSR build ----------------
__global__ void zero_kernel() {
    int i = blockIdx.x * blockDim.x + threadIdx.x;
    if (i < N_NODES) g_cnt[i] = 0;
    if (i < N_GRAPHS * HID) g_gsum[i] = 0.0f;
    if (i < N_GRAPHS) g_gcnt[i] = 0.0f;
}

__global__ void hist_kernel(const int* __restrict__ dst) {
    int e4 = blockIdx.x * blockDim.x + threadIdx.x;
    if (e4 < N_EDGES / 4) {
        int4 d = ((const int4*)dst)[e4];
        atomicAdd(&g_cnt[d.x], 1);
        atomicAdd(&g_cnt[d.y], 1);
        atomicAdd(&g_cnt[d.z], 1);
        atomicAdd(&g_cnt[d.w], 1);
    }
}

// level-1: per-block sums of g_cnt
__global__ void scan1_kernel() {
    __shared__ int ws[8];
    int tid = threadIdx.x, lane = tid & 31, w = tid >> 5;
    int i = blockIdx.x * 256 + tid;
    int v = (i < N_NODES) ? g_cnt[i] : 0;
    #pragma unroll
    for (int off = 16; off > 0; off >>= 1)
        v += __shfl_down_sync(0xffffffffu, v, off);
    if (lane == 0) ws[w] = v;
    __syncthreads();
    if (tid == 0) {
        int s = 0;
        #pragma unroll
        for (int j = 0; j < 8; j++) s += ws[j];
        g_bsum[blockIdx.x] = s;
    }
}

// level-2+3 merged: every block redundantly scans the 196 block sums
// to get its own offset, then scans its 256-element slice of g_cnt.
__global__ void scan3m_kernel() {
    __shared__ int ws[8];
    __shared__ int s_boff;
    int tid = threadIdx.x, lane = tid & 31, w = tid >> 5;

    // phase A: exclusive prefix of g_bsum at index blockIdx.x
    int v = (tid < SCAN_BLOCKS) ? g_bsum[tid] : 0;
    int x = v;
    #pragma unroll
    for (int off = 1; off < 32; off <<= 1) {
        int t = __shfl_up_sync(0xffffffffu, x, off);
        if (lane >= off) x += t;
    }
    if (lane == 31) ws[w] = x;
    __syncthreads();
    if (w == 0 && lane < 8) {
        int y = ws[lane];
        #pragma unroll
        for (int off = 1; off < 8; off <<= 1) {
            int t = __shfl_up_sync(0xffu, y, off);
            if (lane >= off) y += t;
        }
        ws[lane] = y;
    }
    __syncthreads();
    int incl = x + (w > 0 ? ws[w - 1] : 0);
    if (tid == blockIdx.x) s_boff = incl - v;
    if (blockIdx.x == 0 && tid == 0) g_rowptr[0] = 0;
    __syncthreads();

    // phase B: scan this block's slice of g_cnt
    int i = blockIdx.x * 256 + tid;
    int c = (i < N_NODES) ? g_cnt[i] : 0;
    int y = c;
    #pragma unroll
    for (int off = 1; off < 32; off <<= 1) {
        int t = __shfl_up_sync(0xffffffffu, y, off);
        if (lane >= off) y += t;
    }
    if (lane == 31) ws[w] = y;
    __syncthreads();
    if (w == 0 && lane < 8) {
        int z = ws[lane];
        #pragma unroll
        for (int off = 1; off < 8; off <<= 1) {
            int t = __shfl_up_sync(0xffu, z, off);
            if (lane >= off) z += t;
        }
        ws[lane] = z;
    }
    __syncthreads();
    int inc2 = y + (w > 0 ? ws[w - 1] : 0) + s_boff;
    if (i < N_NODES) {
        g_rowptr[i + 1] = inc2;
        g_cursor[i] = inc2 - c;
    }
}

__global__ void fill_kernel(const int* __restrict__ src,
                            const int* __restrict__ dst) {
    int e4 = blockIdx.x * blockDim.x + threadIdx.x;
    if (e4 < N_EDGES / 4) {
        int4 d = ((const int4*)dst)[e4];
        int4 s = ((const int4*)src)[e4];
        g_col[atomicAdd(&g_cursor[d.x], 1)] = s.x;
        g_col[atomicAdd(&g_cursor[d.y], 1)] = s.y;
        g_col[atomicAdd(&g_cursor[d.z], 1)] = s.z;
        g_col[atomicAdd(&g_cursor[d.w], 1)] = s.w;
    }
}

// ------- fused aggregation: out = relu(partial + mean_{j in N(i)} P_j) -------
// warp per node; P is bf16 (256B rows): lane loads uint2 = 4 bf16.
__global__ void aggf_kernel(const __nv_bfloat16* __restrict__ P,
                            const float* __restrict__ partial,
                            float* __restrict__ out) {
    int node = (blockIdx.x * blockDim.x + threadIdx.x) >> 5;
    int lane = threadIdx.x & 31;
    if (node >= N_NODES) return;
    int s = g_rowptr[node];
    int e = g_rowptr[node + 1];
    float4 acc = make_float4(0.f, 0.f, 0.f, 0.f);
    for (int j = s; j < e; j++) {
        int sn = g_col[j];
        uint2 v = *((const uint2*)(P + (size_t)sn * HID) + lane);
        float2 f0 = __bfloat1622float2(*reinterpret_cast<__nv_bfloat162*>(&v.x));
        float2 f1 = __bfloat1622float2(*reinterpret_cast<__nv_bfloat162*>(&v.y));
        acc.x += f0.x; acc.y += f0.y; acc.z += f1.x; acc.w += f1.y;
    }
    int deg = e - s;
    float inv = 1.0f / (float)(deg > 0 ? deg : 1);
    float4 p = *(const float4*)(partial + (size_t)node * HID + lane * 4);
    float4 o;
    o.x = fmaxf(p.x + acc.x * inv, 0.f);
    o.y = fmaxf(p.y + acc.y * inv, 0.f);
    o.z = fmaxf(p.z + acc.z * inv, 0.f);
    o.w = fmaxf(p.w + acc.w * inv, 0.f);
    *(float4*)(out + (size_t)node * HID + lane * 4) = o;
}

// ---------------- pooling (batch is sorted) ----------------
__global__ void pool_kernel(const float* __restrict__ h,
                            const int* __restrict__ batch) {
    int t = threadIdx.x;
    int r0 = blockIdx.x * 128;
    if (r0 >= N_NODES) return;
    int r1 = r0 + 128; if (r1 > N_NODES) r1 = N_NODES;
    int gprev = batch[r0];
    float acc = 0.0f;
    float cacc = 0.0f;
    for (int r = r0; r < r1; r++) {
        int g = batch[r];
        if (g != gprev) {
            atomicAdd(&g_gsum[gprev * HID + t], acc);
            if (t == 0) atomicAdd(&g_gcnt[gprev], cacc);
            acc = 0.0f; cacc = 0.0f; gprev = g;
        }
        acc += h[(size_t)r * HID + t];
        cacc += 1.0f;
    }
    atomicAdd(&g_gsum[gprev * HID + t], acc);
    if (t == 0) atomicAdd(&g_gcnt[gprev], cacc);
}

// ---------------- final: out[g][o] = mean_pool @ fc^T + fc_b ----------------
__global__ void final_kernel(const float* __restrict__ fcW,
                             const float* __restrict__ fcb,
                             float* __restrict__ out) {
    int t = threadIdx.x;
    if (t >= N_GRAPHS * D_OUT) return;
    int g = t / D_OUT, o = t % D_OUT;
    float cnt = g_gcnt[g];
    float inv = 1.0f / fmaxf(cnt, 1.0f);
    float s = 0.0f;
    #pragma unroll 8
    for (int k = 0; k < HID; k++)
        s += g_gsum[g * HID + k] * fcW[o * HID + k];
    out[g * D_OUT + o] = s * inv + fcb[o];
}

// ---------------- launch ----------------
extern "C" void kernel_launch(void* const* d_in, const int* in_sizes, int n_in,
                              void* d_out, int out_size) {
    const float* x    = (const float*)d_in[0];
    const float* Wl0  = (const float*)d_in[1];
    const float* bl0  = (const float*)d_in[2];
    const float* Wr0  = (const float*)d_in[3];
    const float* W1   = (const float*)d_in[4];
    const float* b1   = (const float*)d_in[5];
    const float* Wl1  = (const float*)d_in[6];
    const float* bl1  = (const float*)d_in[7];
    const float* Wr1  = (const float*)d_in[8];
    const float* fcW  = (const float*)d_in[9];
    const float* fcb  = (const float*)d_in[10];
    const int*   ei   = (const int*)d_in[11];     // int64 ref -> int32 harness
    const int*   batch= (const int*)d_in[12];
    float*       out  = (float*)d_out;

    const int* src = ei;
    const int* dst = ei + N_EDGES;

    void *pP = nullptr, *pA = nullptr, *pB = nullptr;
    cudaGetSymbolAddress(&pP, g_P);
    cudaGetSymbolAddress(&pA, g_bufA);
    cudaGetSymbolAddress(&pB, g_bufB);
    __nv_bfloat16* P = (__nv_bfloat16*)pP;
    float* bufA = (float*)pA;
    float* bufB = (float*)pB;

    const int SMEM_D = 3 * 16384 * sizeof(float);   // 196608 (dual)
    const int SMEM_S = 2 * 16384 * sizeof(float);   // 131072 (single)
    cudaFuncSetAttribute(gemm_dw<1>, cudaFuncAttributeMaxDynamicSharedMemorySize, SMEM_D);
    cudaFuncSetAttribute(gemm_dw<0>, cudaFuncAttributeMaxDynamicSharedMemorySize, SMEM_S);

    // side stream + events, created ONCE on first (non-captured) call
    static cudaStream_t s2 = nullptr;
    static cudaEvent_t evFork = nullptr, evJoin = nullptr;
    if (s2 == nullptr) {
        cudaStreamCreateWithFlags(&s2, cudaStreamNonBlocking);
        cudaEventCreateWithFlags(&evFork, cudaEventDisableTiming);
        cudaEventCreateWithFlags(&evJoin, cudaEventDisableTiming);
    }

    int gemm_blocks = (N_NODES + 127) / 128;   // 391

    // fork: CSR build on s2, conv0 dual GEMM on main stream (independent)
    cudaEventRecord(evFork, 0);
    cudaStreamWaitEvent(s2, evFork, 0);

    zero_kernel<<<(N_NODES + 255) / 256, 256, 0, s2>>>();
    hist_kernel<<<(N_EDGES / 4 + 255) / 256, 256, 0, s2>>>(dst);
    scan1_kernel<<<SCAN_BLOCKS, 256, 0, s2>>>();

    // conv0 on main stream (submission position 4 for ncu)
    gemm_dw<1><<<gemm_blocks, 512, SMEM_D>>>(x, Wr0, Wl0, bl0, bufA, P, N_NODES, 0);

    scan3m_kernel<<<SCAN_BLOCKS, 256, 0, s2>>>();
    fill_kernel<<<(N_EDGES / 4 + 255) / 256, 256, 0, s2>>>(src, dst);

    // join: aggf needs CSR + conv0 outputs
    cudaEventRecord(evJoin, s2);
    cudaStreamWaitEvent(0, evJoin, 0);

    // conv0 combine: bufB = relu(partial + agg(P))
    aggf_kernel<<<(N_NODES + 7) / 8, 256>>>(P, bufA, bufB);

    // lin1: bufA = relu(bufB@W1^T + b1)
    gemm_dw<0><<<gemm_blocks, 512, SMEM_S>>>(bufB, W1, nullptr, b1, bufA, nullptr, N_NODES, 1);

    // conv1: partial = bufA@Wr1^T + bl1 (bufB), P = bf16(bufA@Wl1^T)
    gemm_dw<1><<<gemm_blocks, 512, SMEM_D>>>(bufA, Wr1, Wl1, bl1, bufB, P, N_NODES, 0);
    aggf_kernel<<<(N_NODES + 7) / 8, 256>>>(P, bufB, bufA);

    // pool + fc
    pool_kernel<<<(N_NODES + 127) / 128, 128>>>(bufA, batch);
    final_kernel<<<1, 96>>>(fcW, fcb, out);
}

// round 9
// speedup vs baseline: 1.0024x; 1.0024x over previous
#include <cuda_runtime.h>
#include <cuda_bf16.h>
#include <cstdint>

#define N_NODES 50000
#define N_EDGES 600000
#define HID     128
#define N_GRAPHS 32
#define D_OUT   3
#define SCAN_BLOCKS ((N_NODES + 255) / 256)   // 196

typedef unsigned long long u64;

// ---------------- scratch (device globals; no allocs) ----------------
__device__ int   g_cnt[N_NODES];
__device__ int   g_rowptr[N_NODES + 1];
__device__ int   g_cursor[N_NODES];
__device__ int   g_col[N_EDGES];
__device__ int   g_bsum[SCAN_BLOCKS];
__device__ __nv_bfloat16 g_P[(size_t)N_NODES * HID];   // messages, bf16
__device__ float g_bufA[(size_t)N_NODES * HID];
__device__ float g_bufB[(size_t)N_NODES * HID];
__device__ float g_gsum[N_GRAPHS * HID];
__device__ float g_gcnt[N_GRAPHS];

// ---------------- f32x2 helpers ----------------
__device__ __forceinline__ u64 pack_dup(float a) {
    u64 r;
    asm("mov.b64 %0, {%1,%1};" : "=l"(r) : "f"(a));
    return r;
}
__device__ __forceinline__ float2 unpack2(u64 v) {
    float2 r;
    asm("mov.b64 {%0,%1}, %2;" : "=f"(r.x), "=f"(r.y) : "l"(v));
    return r;
}
__device__ __forceinline__ void ffma2(u64& acc, u64 a, u64 b) {
    asm("fma.rn.f32x2 %0, %1, %2, %0;" : "+l"(acc) : "l"(a), "l"(b));
}

// A^T staged layout: element (row, k) lives at sInT[k*128 + (row ^ (k & 31))].
// For an 8-aligned row block r0: words k*128 + (r0 ^ (k&24)) .. +7 hold rows
// r0+(m^(k&7)) — with unroll-8, (k&7) is compile-time so unpermute is static.

// stage a 128x128 fp32 tile transposed+swizzled (all 256 threads)
__device__ __forceinline__ void stage_AT(float* sInT, const float* __restrict__ A,
                                         int m0, int M, int lane, int sub) {
    #pragma unroll
    for (int it = 0; it < 16; it++) {
        int row = it * 8 + sub;
        int grow = m0 + row;
        float4 v = make_float4(0.f, 0.f, 0.f, 0.f);
        if (grow < M) v = *(const float4*)(A + (size_t)grow * 128 + lane * 4);
        int k0 = lane << 2;
        float vv[4] = {v.x, v.y, v.z, v.w};
        #pragma unroll
        for (int i = 0; i < 4; i++) {
            int k = k0 + i;
            sInT[k * 128 + (row ^ (k & 31))] = vv[i];
        }
    }
}

// stage one weight matrix k-major, float4 XOR-swizzled along cols:
// logical (k, c4) lives at sW[k*128 + ((c4 ^ ((k>>2)&31))<<2)]
__device__ __forceinline__ void stage_W(float* sW, const float* __restrict__ W,
                                        int lane, int sub) {
    #pragma unroll
    for (int it = 0; it < 16; it++) {
        int col = it * 8 + sub;
        int c4 = col >> 2, cl = col & 3;
        float4 v = *(const float4*)(W + col * 128 + (lane << 2));
        float vv[4] = {v.x, v.y, v.z, v.w};
        #pragma unroll
        for (int i = 0; i < 4; i++) {
            int k = (lane << 2) + i;     // (k>>2)&31 == lane
            sW[k * 128 + ((c4 ^ lane) << 2) + cl] = vv[i];
        }
    }
}

// =================================================================
// conv dual GEMM: out1 = A@W1^T + bias [fp32], out2 = bf16(A@W2^T)
// 128x128 tile, 256 threads, 8x8 microtile, fma.rn.f32x2, A^T staging.
// =================================================================
__global__ void __launch_bounds__(256, 1)
gemm_dual(const float* __restrict__ A,
          const float* __restrict__ W1, const float* __restrict__ W2,
          const float* __restrict__ bias,
          float* __restrict__ out1, __nv_bfloat16* __restrict__ out2, int M) {
    extern __shared__ float smem[];
    float* sInT = smem;
    float* sW1 = smem + 16384;
    float* sW2 = smem + 32768;

    int tid = threadIdx.x;
    int lane = tid & 31, sub = tid >> 5;
    int tx = tid & 15, ty = tid >> 4;
    int m0 = blockIdx.x * 128;

    stage_AT(sInT, A, m0, M, lane, sub);
    stage_W(sW1, W1, lane, sub);
    stage_W(sW2, W2, lane, sub);
    __syncthreads();

    u64 acc1[8][4], acc2[8][4];
    #pragma unroll
    for (int r = 0; r < 8; r++)
        #pragma unroll
        for (int c = 0; c < 4; c++) { acc1[r][c] = 0ull; acc2[r][c] = 0ull; }

    int r0 = ty * 8;
    #pragma unroll 1
    for (int k8 = 0; k8 < 16; k8++) {
        #pragma unroll
        for (int u = 0; u < 8; u++) {
            int k = k8 * 8 + u;
            const float* ab = sInT + k * 128 + (r0 ^ (k & 24));
            float4 fa = *(const float4*)ab;
            float4 fb = *(const float4*)(ab + 4);
            float v[8] = {fa.x, fa.y, fa.z, fa.w, fb.x, fb.y, fb.z, fb.w};
            u64 a2[8];
            #pragma unroll
            for (int j = 0; j < 8; j++) a2[j] = pack_dup(v[j ^ u]);
            int swz = (k >> 2) & 31;
            const float* w1r = sW1 + k * 128;
            ulonglong2 p0 = *(const ulonglong2*)(w1r + ((((tx << 1)    ) ^ swz) << 2));
            ulonglong2 p1 = *(const ulonglong2*)(w1r + ((((tx << 1) | 1) ^ swz) << 2));
            u64 b1v[4] = {p0.x, p0.y, p1.x, p1.y};
            #pragma unroll
            for (int r = 0; r < 8; r++)
                #pragma unroll
                for (int c = 0; c < 4; c++)
                    ffma2(acc1[r][c], a2[r], b1v[c]);
            const float* w2r = sW2 + k * 128;
            ulonglong2 q0 = *(const ulonglong2*)(w2r + ((((tx << 1)    ) ^ swz) << 2));
            ulonglong2 q1 = *(const ulonglong2*)(w2r + ((((tx << 1) | 1) ^ swz) << 2));
            u64 b2v[4] = {q0.x, q0.y, q1.x, q1.y};
            #pragma unroll
            for (int r = 0; r < 8; r++)
                #pragma unroll
                for (int c = 0; c < 4; c++)
                    ffma2(acc2[r][c], a2[r], b2v[c]);
        }
    }

    float bv[8];
    #pragma unroll
    for (int j = 0; j < 8; j++) bv[j] = bias[tx * 8 + j];

    #pragma unroll
    for (int r = 0; r < 8; r++) {
        int grow = m0 + ty * 8 + r;
        if (grow < M) {
            float o[8];
            #pragma unroll
            for (int c = 0; c < 4; c++) {
                float2 v = unpack2(acc1[r][c]);
                o[2 * c]     = v.x + bv[2 * c];
                o[2 * c + 1] = v.y + bv[2 * c + 1];
            }
            float4* d1 = (float4*)(out1 + (size_t)grow * 128 + tx * 8);
            d1[0] = make_float4(o[0], o[1], o[2], o[3]);
            d1[1] = make_float4(o[4], o[5], o[6], o[7]);
            __nv_bfloat162 h[4];
            #pragma unroll
            for (int c = 0; c < 4; c++) {
                float2 v = unpack2(acc2[r][c]);
                h[c] = __float22bfloat162_rn(v);
            }
            uint4 pk;
            pk.x = *(uint32_t*)&h[0];
            pk.y = *(uint32_t*)&h[1];
            pk.z = *(uint32_t*)&h[2];
            pk.w = *(uint32_t*)&h[3];
            *(uint4*)(out2 + (size_t)grow * 128 + tx * 8) = pk;
        }
    }
}

// =================================================================
// fused lin1 + conv1: h = relu(A@W1^T + b1) (kept in smem),
// then out1 = h@Wr^T + blr [fp32], out2 = bf16(h@Wl^T)
// =================================================================
__global__ void __launch_bounds__(256, 1)
gemm_fused(const float* __restrict__ A,
           const float* __restrict__ W1, const float* __restrict__ b1,
           const float* __restrict__ Wr, const float* __restrict__ Wl,
           const float* __restrict__ blr,
           float* __restrict__ out1, __nv_bfloat16* __restrict__ out2, int M) {
    extern __shared__ float smem[];
    float* sInT = smem;
    float* sW1 = smem + 16384;
    float* sW2 = smem + 32768;

    int tid = threadIdx.x;
    int lane = tid & 31, sub = tid >> 5;
    int tx = tid & 15, ty = tid >> 4;
    int m0 = blockIdx.x * 128;
    int r0 = ty * 8;

    // ---- phase 1: lin1 single GEMM ----
    stage_AT(sInT, A, m0, M, lane, sub);
    stage_W(sW1, W1, lane, sub);
    __syncthreads();

    u64 acc1[8][4], acc2[8][4];
    #pragma unroll
    for (int r = 0; r < 8; r++)
        #pragma unroll
        for (int c = 0; c < 4; c++) acc1[r][c] = 0ull;

    #pragma unroll 1
    for (int k8 = 0; k8 < 16; k8++) {
        #pragma unroll
        for (int u = 0; u < 8; u++) {
            int k = k8 * 8 + u;
            const float* ab = sInT + k * 128 + (r0 ^ (k & 24));
            float4 fa = *(const float4*)ab;
            float4 fb = *(const float4*)(ab + 4);
            float v[8] = {fa.x, fa.y, fa.z, fa.w, fb.x, fb.y, fb.z, fb.w};
            u64 a2[8];
            #pragma unroll
            for (int j = 0; j < 8; j++) a2[j] = pack_dup(v[j ^ u]);
            int swz = (k >> 2) & 31;
            const float* w1r = sW1 + k * 128;
            ulonglong2 p0 = *(const ulonglong2*)(w1r + ((((tx << 1)    ) ^ swz) << 2));
            ulonglong2 p1 = *(const ulonglong2*)(w1r + ((((tx << 1) | 1) ^ swz) << 2));
            u64 b1v[4] = {p0.x, p0.y, p1.x, p1.y};
            #pragma unroll
            for (int r = 0; r < 8; r++)
                #pragma unroll
                for (int c = 0; c < 4; c++)
                    ffma2(acc1[r][c], a2[r], b1v[c]);
        }
    }
    __syncthreads();   // all reads of sInT/sW1 done

    // ---- phase 2: h = relu(acc + b1) -> sInT (transposed, swizzled) ----
    {
        float bv1[8];
        #pragma unroll
        for (int j = 0; j < 8; j++) bv1[j] = b1[tx * 8 + j];
        #pragma unroll
        for (int r = 0; r < 8; r++) {
            int row = r0 + r;
            #pragma unroll
            for (int c4 = 0; c4 < 4; c4++) {
                float2 vv = unpack2(acc1[r][c4]);
                int col0 = tx * 8 + c4 * 2;
                float h0 = fmaxf(vv.x + bv1[c4 * 2], 0.f);
                float h1 = fmaxf(vv.y + bv1[c4 * 2 + 1], 0.f);
                sInT[col0 * 128 + (row ^ (col0 & 31))] = h0;
                sInT[(col0 + 1) * 128 + (row ^ ((col0 + 1) & 31))] = h1;
            }
        }
    }
    stage_W(sW1, Wr, lane, sub);
    stage_W(sW2, Wl, lane, sub);
    __syncthreads();

    // ---- phase 3: conv1 dual GEMM from h ----
    #pragma unroll
    for (int r = 0; r < 8; r++)
        #pragma unroll
        for (int c = 0; c < 4; c++) { acc1[r][c] = 0ull; acc2[r][c] = 0ull; }

    #pragma unroll 1
    for (int k8 = 0; k8 < 16; k8++) {
        #pragma unroll
        for (int u = 0; u < 8; u++) {
            int k = k8 * 8 + u;
            const float* ab = sInT + k * 128 + (r0 ^ (k & 24));
            float4 fa = *(const float4*)ab;
            float4 fb = *(const float4*)(ab + 4);
            float v[8] = {fa.x, fa.y, fa.z, fa.w, fb.x, fb.y, fb.z, fb.w};
            u64 a2[8];
            #pragma unroll
            for (int j = 0; j < 8; j++) a2[j] = pack_dup(v[j ^ u]);
            int swz = (k >> 2) & 31;
            const float* w1r = sW1 + k * 128;
            ulonglong2 p0 = *(const ulonglong2*)(w1r + ((((tx << 1)    ) ^ swz) << 2));
            ulonglong2 p1 = *(const ulonglong2*)(w1r + ((((tx << 1) | 1) ^ swz) << 2));
            u64 b1v[4] = {p0.x, p0.y, p1.x, p1.y};
            #pragma unroll
            for (int r = 0; r < 8; r++)
                #pragma unroll
                for (int c = 0; c < 4; c++)
                    ffma2(acc1[r][c], a2[r], b1v[c]);
            const float* w2r = sW2 + k * 128;
            ulonglong2 q0 = *(const ulonglong2*)(w2r + ((((tx << 1)    ) ^ swz) << 2));
            ulonglong2 q1 = *(const ulonglong2*)(w2r + ((((tx << 1) | 1) ^ swz) << 2));
            u64 b2v[4] = {q0.x, q0.y, q1.x, q1.y};
            #pragma unroll
            for (int r = 0; r < 8; r++)
                #pragma unroll
                for (int c = 0; c < 4; c++)
                    ffma2(acc2[r][c], a2[r], b2v[c]);
        }
    }

    float bv[8];
    #pragma unroll
    for (int j = 0; j < 8; j++) bv[j] = blr[tx * 8 + j];

    #pragma unroll
    for (int r = 0; r < 8; r++) {
        int grow = m0 + r0 + r;
        if (grow < M) {
            float o[8];
            #pragma unroll
            for (int c = 0; c < 4; c++) {
                float2 v = unpack2(acc1[r][c]);
                o[2 * c]     = v.x + bv[2 * c];
                o[2 * c + 1] = v.y + bv[2 * c + 1];
            }
            float4* d1 = (float4*)(out1 + (size_t)grow * 128 + tx * 8);
            d1[0] = make_float4(o[0], o[1], o[2], o[3]);
            d1[1] = make_float4(o[4], o[5], o[6], o[7]);
            __nv_bfloat162 h[4];
            #pragma unroll
            for (int c = 0; c < 4; c++) {
                float2 v = unpack2(acc2[r][c]);
                h[c] = __float22bfloat162_rn(v);
            }
            uint4 pk;
            pk.x = *(uint32_t*)&h[0];
            pk.y = *(uint32_t*)&h[1];
            pk.z = *(uint32_t*)&h[2];
            pk.w = *(uint32_t*)&h[3];
            *(uint4*)(out2 + (size_t)grow * 128 + tx * 8) = pk;
        }
    }
}

// ---------------- CSR build ----------------
__global__ void zero_kernel() {
    int i = blockIdx.x * blockDim.x + threadIdx.x;
    if (i < N_NODES) g_cnt[i] = 0;
    if (i < N_GRAPHS * HID) g_gsum[i] = 0.0f;
    if (i < N_GRAPHS) g_gcnt[i] = 0.0f;
}

__global__ void hist_kernel(const int* __restrict__ dst) {
    int e4 = blockIdx.x * blockDim.x + threadIdx.x;
    if (e4 < N_EDGES / 4) {
        int4 d = ((const int4*)dst)[e4];
        atomicAdd(&g_cnt[d.x], 1);
        atomicAdd(&g_cnt[d.y], 1);
        atomicAdd(&g_cnt[d.z], 1);
        atomicAdd(&g_cnt[d.w], 1);
    }
}

__global__ void scan1_kernel() {
    __shared__ int ws[8];
    int tid = threadIdx.x, lane = tid & 31, w = tid >> 5;
    int i = blockIdx.x * 256 + tid;
    int v = (i < N_NODES) ? g_cnt[i] : 0;
    #pragma unroll
    for (int off = 16; off > 0; off >>= 1)
        v += __shfl_down_sync(0xffffffffu, v, off);
    if (lane == 0) ws[w] = v;
    __syncthreads();
    if (tid == 0) {
        int s = 0;
        #pragma unroll
        for (int j = 0; j < 8; j++) s += ws[j];
        g_bsum[blockIdx.x] = s;
    }
}

__global__ void scan3m_kernel() {
    __shared__ int ws[8];
    __shared__ int s_boff;
    int tid = threadIdx.x, lane = tid & 31, w = tid >> 5;

    int v = (tid < SCAN_BLOCKS) ? g_bsum[tid] : 0;
    int x = v;
    #pragma unroll
    for (int off = 1; off < 32; off <<= 1) {
        int t = __shfl_up_sync(0xffffffffu, x, off);
        if (lane >= off) x += t;
    }
    if (lane == 31) ws[w] = x;
    __syncthreads();
    if (w == 0 && lane < 8) {
        int y = ws[lane];
        #pragma unroll
        for (int off = 1; off < 8; off <<= 1) {
            int t = __shfl_up_sync(0xffu, y, off);
            if (lane >= off) y += t;
        }
        ws[lane] = y;
    }
    __syncthreads();
    int incl = x + (w > 0 ? ws[w - 1] : 0);
    if (tid == blockIdx.x) s_boff = incl - v;
    if (blockIdx.x == 0 && tid == 0) g_rowptr[0] = 0;
    __syncthreads();

    int i = blockIdx.x * 256 + tid;
    int c = (i < N_NODES) ? g_cnt[i] : 0;
    int y = c;
    #pragma unroll
    for (int off = 1; off < 32; off <<= 1) {
        int t = __shfl_up_sync(0xffffffffu, y, off);
        if (lane >= off) y += t;
    }
    if (lane == 31) ws[w] = y;
    __syncthreads();
    if (w == 0 && lane < 8) {
        int z = ws[lane];
        #pragma unroll
        for (int off = 1; off < 8; off <<= 1) {
            int t = __shfl_up_sync(0xffu, z, off);
            if (lane >= off) z += t;
        }
        ws[lane] = z;
    }
    __syncthreads();
    int inc2 = y + (w > 0 ? ws[w - 1] : 0) + s_boff;
    if (i < N_NODES) {
        g_rowptr[i + 1] = inc2;
        g_cursor[i] = inc2 - c;
    }
}

__global__ void fill_kernel(const int* __restrict__ src,
                            const int* __restrict__ dst) {
    int e4 = blockIdx.x * blockDim.x + threadIdx.x;
    if (e4 < N_EDGES / 4) {
        int4 d = ((const int4*)dst)[e4];
        int4 s = ((const int4*)src)[e4];
        g_col[atomicAdd(&g_cursor[d.x], 1)] = s.x;
        g_col[atomicAdd(&g_cursor[d.y], 1)] = s.y;
        g_col[atomicAdd(&g_cursor[d.z], 1)] = s.z;
        g_col[atomicAdd(&g_cursor[d.w], 1)] = s.w;
    }
}

// ------- fused aggregation: out = relu(partial + mean_{j in N(i)} P_j) -------
__global__ void aggf_kernel(const __nv_bfloat16* __restrict__ P,
                            const float* __restrict__ partial,
                            float* __restrict__ out) {
    int node = (blockIdx.x * blockDim.x + threadIdx.x) >> 5;
    int lane = threadIdx.x & 31;
    if (node >= N_NODES) return;
    int s = g_rowptr[node];
    int e = g_rowptr[node + 1];
    float4 acc = make_float4(0.f, 0.f, 0.f, 0.f);
    for (int j = s; j < e; j++) {
        int sn = g_col[j];
        uint2 v = *((const uint2*)(P + (size_t)sn * HID) + lane);
        float2 f0 = __bfloat1622float2(*reinterpret_cast<__nv_bfloat162*>(&v.x));
        float2 f1 = __bfloat1622float2(*reinterpret_cast<__nv_bfloat162*>(&v.y));
        acc.x += f0.x; acc.y += f0.y; acc.z += f1.x; acc.w += f1.y;
    }
    int deg = e - s;
    float inv = 1.0f / (float)(deg > 0 ? deg : 1);
    float4 p = *(const float4*)(partial + (size_t)node * HID + lane * 4);
    float4 o;
    o.x = fmaxf(p.x + acc.x * inv, 0.f);
    o.y = fmaxf(p.y + acc.y * inv, 0.f);
    o.z = fmaxf(p.z + acc.z * inv, 0.f);
    o.w = fmaxf(p.w + acc.w * inv, 0.f);
    *(float4*)(out + (size_t)node * HID + lane * 4) = o;
}

// ---------------- pooling (batch is sorted) ----------------
__global__ void pool_kernel(const float* __restrict__ h,
                            const int* __restrict__ batch) {
    int t = threadIdx.x;
    int r0 = blockIdx.x * 128;
    if (r0 >= N_NODES) return;
    int r1 = r0 + 128; if (r1 > N_NODES) r1 = N_NODES;
    int gprev = batch[r0];
    float acc = 0.0f;
    float cacc = 0.0f;
    for (int r = r0; r < r1; r++) {
        int g = batch[r];
        if (g != gprev) {
            atomicAdd(&g_gsum[gprev * HID + t], acc);
            if (t == 0) atomicAdd(&g_gcnt[gprev], cacc);
            acc = 0.0f; cacc = 0.0f; gprev = g;
        }
        acc += h[(size_t)r * HID + t];
        cacc += 1.0f;
    }
    atomicAdd(&g_gsum[gprev * HID + t], acc);
    if (t == 0) atomicAdd(&g_gcnt[gprev], cacc);
}

// ---------------- final: out[g][o] = mean_pool @ fc^T + fc_b ----------------
__global__ void final_kernel(const float* __restrict__ fcW,
                             const float* __restrict__ fcb,
                             float* __restrict__ out) {
    int t = threadIdx.x;
    if (t >= N_GRAPHS * D_OUT) return;
    int g = t / D_OUT, o = t % D_OUT;
    float cnt = g_gcnt[g];
    float inv = 1.0f / fmaxf(cnt, 1.0f);
    float s = 0.0f;
    #pragma unroll 8
    for (int k = 0; k < HID; k++)
        s += g_gsum[g * HID + k] * fcW[o * HID + k];
    out[g * D_OUT + o] = s * inv + fcb[o];
}

// ---------------- launch ----------------
extern "C" void kernel_launch(void* const* d_in, const int* in_sizes, int n_in,
                              void* d_out, int out_size) {
    const float* x    = (const float*)d_in[0];
    const float* Wl0  = (const float*)d_in[1];
    const float* bl0  = (const float*)d_in[2];
    const float* Wr0  = (const float*)d_in[3];
    const float* W1   = (const float*)d_in[4];
    const float* b1   = (const float*)d_in[5];
    const float* Wl1  = (const float*)d_in[6];
    const float* bl1  = (const float*)d_in[7];
    const float* Wr1  = (const float*)d_in[8];
    const float* fcW  = (const float*)d_in[9];
    const float* fcb  = (const float*)d_in[10];
    const int*   ei   = (const int*)d_in[11];     // int64 ref -> int32 harness
    const int*   batch= (const int*)d_in[12];
    float*       out  = (float*)d_out;

    const int* src = ei;
    const int* dst = ei + N_EDGES;

    void *pP = nullptr, *pA = nullptr, *pB = nullptr;
    cudaGetSymbolAddress(&pP, g_P);
    cudaGetSymbolAddress(&pA, g_bufA);
    cudaGetSymbolAddress(&pB, g_bufB);
    __nv_bfloat16* P = (__nv_bfloat16*)pP;
    float* bufA = (float*)pA;
    float* bufB = (float*)pB;

    const int SMEM_D = 3 * 16384 * sizeof(float);   // 196608
    cudaFuncSetAttribute(gemm_dual, cudaFuncAttributeMaxDynamicSharedMemorySize, SMEM_D);
    cudaFuncSetAttribute(gemm_fused, cudaFuncAttributeMaxDynamicSharedMemorySize, SMEM_D);

    // side stream + events, created ONCE on first (non-captured) call
    static cudaStream_t s2 = nullptr;
    static cudaEvent_t evFork = nullptr, evJoin = nullptr;
    if (s2 == nullptr) {
        cudaStreamCreateWithFlags(&s2, cudaStreamNonBlocking);
        cudaEventCreateWithFlags(&evFork, cudaEventDisableTiming);
        cudaEventCreateWithFlags(&evJoin, cudaEventDisableTiming);
    }

    int gemm_blocks = (N_NODES + 127) / 128;   // 391

    // fork: CSR build on s2, conv0 dual GEMM on main stream (independent)
    cudaEventRecord(evFork, 0);
    cudaStreamWaitEvent(s2, evFork, 0);

    zero_kernel<<<(N_NODES + 255) / 256, 256, 0, s2>>>();
    hist_kernel<<<(N_EDGES / 4 + 255) / 256, 256, 0, s2>>>(dst);
    scan1_kernel<<<SCAN_BLOCKS, 256, 0, s2>>>();

    // conv0 on main stream: partial = x@Wr0^T + bl0 -> bufA, P = bf16(x@Wl0^T)
    gemm_dual<<<gemm_blocks, 256, SMEM_D>>>(x, Wr0, Wl0, bl0, bufA, P, N_NODES);

    scan3m_kernel<<<SCAN_BLOCKS, 256, 0, s2>>>();
    fill_kernel<<<(N_EDGES / 4 + 255) / 256, 256, 0, s2>>>(src, dst);

    // join: aggf needs CSR + conv0 outputs
    cudaEventRecord(evJoin, s2);
    cudaStreamWaitEvent(0, evJoin, 0);

    // conv0 combine: bufB = relu(partial + agg(P))
    aggf_kernel<<<(N_NODES + 7) / 8, 256>>>(P, bufA, bufB);

    // fused lin1+conv1: h = relu(bufB@W1^T+b1); partial = h@Wr1^T+bl1 -> bufA, P = bf16(h@Wl1^T)
    gemm_fused<<<gemm_blocks, 256, SMEM_D>>>(bufB, W1, b1, Wr1, Wl1, bl1, bufA, P, N_NODES);

    // conv1 combine: bufB = relu(partial + agg(P))
    aggf_kernel<<<(N_NODES + 7) / 8, 256>>>(P, bufA, bufB);

    // pool + fc
    pool_kernel<<<(N_NODES + 127) / 128, 128>>>(bufB, batch);
    final_kernel<<<1, 96>>>(fcW, fcb, out);
}